// round 17
// baseline (speedup 1.0000x reference)
#include <cuda_runtime.h>
#include <cstdint>

// ---------------------------------------------------------------------------
// Problem constants
// ---------------------------------------------------------------------------
#define KK 16
#define YY 32
#define CC 16
#define NBUCKET (KK * YY)          // 512
#define ACC_ELEMS (NBUCKET * CC)   // 8192
#define NREP 32
#define EPS_F 1e-8f

#define SGRID 592                  // 148 SMs x 4 CTAs x 512 thr = one full wave
#define TPB 512

// 16-bit fixed-point smem sink: values in [0,1), scale 2^11.
// Field capacity 65535 -> >= 64 offloaded values per (CTA, bucket, c4) slot;
// occupancy is Poisson(~4.5) -> overflow prob ~1e-40. Quantization
// +-2^-12/value -> ~2e-6 rel on outputs.
#define SCALE_F 2048.0f            // 2^11
#define INV_SCALE_F (1.0f / 2048.0f)
#define BSTRIDE 5                  // u64 per bucket (4 data + 1 pad, bank spread)

// Replicated scratch: 32 x 8192 f32 = 1 MB. Zero-initialized at module load;
// cc_finalize resets it after reading, so every launch / graph replay enters
// with it zeroed. 16B-aligned for red.v4.
__device__ __align__(16) float g_acc[NREP * ACC_ELEMS];

__device__ __forceinline__ void red_v4(float* dst, float x, float y, float z, float w) {
    asm volatile("red.global.add.v4.f32 [%0], {%1, %2, %3, %4};"
                 :: "l"(dst), "f"(x), "f"(y), "f"(z), "f"(w)
                 : "memory");
}

// ---------------------------------------------------------------------------
// Kernel 1: hybrid scatter at the CALIBRATED balance point.
// Measured model (r13/r15/r16 fits):
//   T_L2(x)   = 25.5 + (1-x)*47.3 us   (reads + RED 32B-sector traffic @ LTS cap)
//   T_smem(x) = 166*x us               (ATOMS.64 + pack ALU on the SM)
// Balance x* ~= 0.34 -> run x = 1/3 via warp-uniform mod-3 phase.
// ---------------------------------------------------------------------------
__global__ void __launch_bounds__(TPB)
cc_scatter(const int* __restrict__ xl,
           const int* __restrict__ yl,
           const float4* __restrict__ post,
           int n_f4) {
    __shared__ unsigned long long s_acc[NBUCKET * BSTRIDE];   // 20,480 B
    int tid = threadIdx.x;
    int wid = tid >> 5;

    // zero smem accumulator
    for (int e = tid; e < NBUCKET * BSTRIDE; e += TPB) s_acc[e] = 0ull;
    __syncthreads();

    float* rep = &g_acc[(blockIdx.x & (NREP - 1)) * ACC_ELEMS];
    int stride = gridDim.x * blockDim.x;
    int phase = wid % 3;                           // warp-uniform mod-3 phase
    for (int i = blockIdx.x * blockDim.x + tid; i < n_f4; i += stride) {
        int row = i >> 2;
        int c4  = i & 3;
        float4 v = post[i];
        int b = xl[row] * YY + yl[row];            // bucket in [0,512)
        if (phase == 0) {
            // smem sink (1/3, warp-uniform): ONE packed u64 atomic
            unsigned long long u0 = (unsigned long long)__float2uint_rn(v.x * SCALE_F);
            unsigned long long u1 = (unsigned long long)__float2uint_rn(v.y * SCALE_F);
            unsigned long long u2 = (unsigned long long)__float2uint_rn(v.z * SCALE_F);
            unsigned long long u3 = (unsigned long long)__float2uint_rn(v.w * SCALE_F);
            unsigned long long p = u0 | (u1 << 16) | (u2 << 32) | (u3 << 48);
            atomicAdd(&s_acc[b * BSTRIDE + c4], p);
        } else {
            // L2 sink (2/3)
            red_v4(&rep[b * CC + c4 * 4], v.x, v.y, v.z, v.w);
        }
        phase = (phase == 2) ? 0 : phase + 1;      // branch-free-ish wrap
    }
    __syncthreads();

    // flush: thread t owns bucket t (TPB == NBUCKET). Fields are exact
    // integer sums of quantized values.
    {
        const unsigned long long* s = &s_acc[tid * BSTRIDE];
        float* dst = &rep[tid * CC];
#pragma unroll
        for (int j = 0; j < 4; j++) {
            unsigned long long a = s[j];
            float f0 = (float)(unsigned int)( a        & 0xFFFF) * INV_SCALE_F;
            float f1 = (float)(unsigned int)((a >> 16) & 0xFFFF) * INV_SCALE_F;
            float f2 = (float)(unsigned int)((a >> 32) & 0xFFFF) * INV_SCALE_F;
            float f3 = (float)(unsigned int)((a >> 48) & 0xFFFF) * INV_SCALE_F;
            red_v4(dst + j * 4, f0, f1, f2, f3);
        }
    }
}

// ---------------------------------------------------------------------------
// Kernel 2: finalize (verbatim since r9). 16 blocks (one per k), 512 threads
// (one per (y,c)): replica-sum (MLP=32), Y-normalize, write, reset scratch.
// ---------------------------------------------------------------------------
__global__ void __launch_bounds__(512)
cc_finalize(float* __restrict__ out) {
    __shared__ float s_val[YY * CC];
    __shared__ float s_inv[CC];

    int k   = blockIdx.x;                // 0..15
    int tid = threadIdx.x;               // 0..511
    int elem = k * (YY * CC) + tid;

    float s = 0.0f;
#pragma unroll
    for (int r = 0; r < NREP; r++)
        s += g_acc[r * ACC_ELEMS + elem];
    float v = s + EPS_F;
    s_val[tid] = v;
    __syncthreads();

    if (tid < CC) {
        float d = 0.0f;
#pragma unroll
        for (int y = 0; y < YY; y++)
            d += s_val[y * CC + tid];
        s_inv[tid] = 1.0f / d;
    }
    __syncthreads();

    out[elem] = v * s_inv[tid & 15];

    // reset this element's replica slots for the next launch / graph replay
#pragma unroll
    for (int r = 0; r < NREP; r++)
        g_acc[r * ACC_ELEMS + elem] = 0.0f;
}

// ---------------------------------------------------------------------------
// Launch
// ---------------------------------------------------------------------------
extern "C" void kernel_launch(void* const* d_in, const int* in_sizes, int n_in,
                              void* d_out, int out_size) {
    const int*    xl   = (const int*)d_in[0];        // x_labels [N] int32
    const int*    yl   = (const int*)d_in[1];        // y_labels [N] int32
    const float4* post = (const float4*)d_in[2];     // posterior [N,16] f32
    float* out = (float*)d_out;                      // [16,32,16] f32

    int n = in_sizes[0];
    int n_f4 = n * (CC / 4);

    static bool attr_set = false;
    if (!attr_set) {
        cudaFuncSetAttribute(cc_scatter,
                             cudaFuncAttributePreferredSharedMemoryCarveout,
                             cudaSharedmemCarveoutMaxShared);
        attr_set = true;
    }

    cc_scatter<<<SGRID, TPB>>>(xl, yl, post, n_f4);
    cc_finalize<<<KK, 512>>>(out);
}